// round 12
// baseline (speedup 1.0000x reference)
#include <cuda_runtime.h>
#include <cuda_fp16.h>
#include <math.h>
#include <cstdint>

#define B_  4
#define T_  2048
#define DH  512
#define H_  8
#define ND  4096
#define BT  8192
#define TM  128
#define TN  128
#define KC  64                           // fp16 elems per chunk = 128B rows
#define NSTAGE 3
#define SSZ (2 * TM * 128)               // stage bytes (A 16KB + B 16KB) = 32768
#define SMEM_BYTES (NSTAGE * SSZ)        // 98304

// ---------------- scratch (device globals: allocation-free) ----------------
__device__ __half g_q  [(size_t)BT * ND];           // q-hat fp16, pair-permuted
__device__ __half g_vt [(size_t)B_ * ND * T_];      // [b][h*DH+d][t-perm] fp16
__device__ __half g_p  [(size_t)B_ * H_ * T_ * T_]; // scores->probs fp16, j-perm
__device__ __half g_mt [(size_t)ND * DH];           // Mt[h*512+e][d] fp16 perm
__device__ __half g_wq16[(size_t)DH * ND];          // Wq fp16 col-permuted
__device__ __half g_wk16[(size_t)DH * ND];          // Wk fp16 col-permuted
__device__ __half g_wvt[(size_t)ND * DH];           // Wv^T fp16 k-permuted
__device__ __half g_qr [(size_t)BT * DH];           // query fp16 k-permuted
__device__ __half g_vr [(size_t)BT * DH];           // value fp16 k-permuted
__device__ float  g_y[H_ * DH], g_z[H_ * DH], g_c[H_];
__device__ float  g_u[(size_t)B_ * H_ * T_];        // row-bias planes
__device__ float  g_w[(size_t)B_ * H_ * T_];        // col-bias planes

__device__ __forceinline__ int tr4(int x) { return ((x & 3) << 2) | (x >> 2); }
__device__ __forceinline__ uint32_t h2u(__half2 h) {
    return *reinterpret_cast<uint32_t*>(&h);
}
__device__ __forceinline__ uint32_t smem_u32(const void* p) {
    uint32_t a;
    asm("{ .reg .u64 t; cvta.to.shared.u64 t, %1; cvt.u32.u64 %0, t; }" : "=r"(a) : "l"(p));
    return a;
}
__device__ __forceinline__ void cp_async16(uint32_t saddr, const void* gaddr) {
    asm volatile("cp.async.cg.shared.global [%0], [%1], 16;" :: "r"(saddr), "l"(gaddr));
}
#define CP_COMMIT() asm volatile("cp.async.commit_group;" ::: "memory")
#define CP_WAIT1()  asm volatile("cp.async.wait_group 1;" ::: "memory")
#define CP_WAIT0()  asm volatile("cp.async.wait_group 0;" ::: "memory")

#define LDS4(v, base, IMM) \
    asm volatile("ld.shared.v4.b32 {%0,%1,%2,%3}, [%4+" IMM "];" \
        : "=r"((v).x), "=r"((v).y), "=r"((v).z), "=r"((v).w) : "r"(base))

__device__ __forceinline__ void mma_f16(float* c,
                                        uint32_t a0, uint32_t a1, uint32_t a2, uint32_t a3,
                                        uint32_t b0, uint32_t b1) {
    asm volatile("mma.sync.aligned.m16n8k16.row.col.f32.f16.f16.f32 "
                 "{%0,%1,%2,%3}, {%4,%5,%6,%7}, {%8,%9}, {%0,%1,%2,%3};"
                 : "+f"(c[0]), "+f"(c[1]), "+f"(c[2]), "+f"(c[3])
                 : "r"(a0), "r"(a1), "r"(a2), "r"(a3), "r"(b0), "r"(b1));
}

// ======================= generic fp16 mma.sync GEMM =======================
struct GemmArgs {
    const __half* A; long long sAz, sAh; int lda;
    const __half* B; long long sBz, sBh; int ldb;
    void*         C; long long sCz, sCh; int ldc;
    int K; int zHeads;
    const float* bias; const float* bias2;
    int biasMode;     // 0 none, 1 by-col, 2 by-row, 3 row(u)+col(w) pre-scale
    float scale;
    int causal;       // 0 none, 1 skip tj>ti, 2 kmax=m0+TM
    int outHalf;      // 1: fp16 pair-permuted out, 0: fp32 plain
};

__global__ __launch_bounds__(256, 2) void gemm_tc(GemmArgs ga)
{
    const int ti = blockIdx.y, tj = blockIdx.x, z = blockIdx.z;
    if (ga.causal == 1 && tj > ti) return;

    extern __shared__ uint32_t smem[];
    const uint32_t sb = smem_u32(smem);

    const int tid  = threadIdx.x;
    const int wid  = tid >> 5, lane = tid & 31;
    const int wm   = wid >> 2, wn = wid & 3;        // 2 x 4 warp grid
    const int gid  = lane >> 2, tig = lane & 3;
    const int m0 = ti * TM, n0 = tj * TN;
    const int px = (gid & 1) << 2;

    int kmax = ga.K;
    if (ga.causal == 2) kmax = min(kmax, m0 + TM);
    const int NC = kmax / KC;

    const int zb = z / ga.zHeads, zh = z - zb * ga.zHeads;
    const __half* Ag = ga.A + (size_t)zb * ga.sAz + (size_t)zh * ga.sAh;
    const __half* Bg = ga.B + (size_t)zb * ga.sBz + (size_t)zh * ga.sBh;

    // ---- producer: rows are 8 chunks of 16B (128B pitch) ----
    int soff[4];
    const __half *pA[4], *pB[4];
#pragma unroll
    for (int i = 0; i < 4; ++i) {
        const int id = i * 256 + tid;
        const int row = id >> 3, ch = id & 7;
        soff[i] = (row * 8 + (ch ^ ((row & 1) << 2))) * 16;
        pA[i] = Ag + (size_t)(m0 + row) * ga.lda + ch * 8;
        pB[i] = Bg + (size_t)(n0 + row) * ga.ldb + ch * 8;
    }
    uint32_t prodBase = sb;
    int ps = 0;

#define ISSUE() do {                                                    \
        _Pragma("unroll")                                               \
        for (int _i = 0; _i < 4; ++_i) {                                \
            cp_async16(prodBase + soff[_i], pA[_i]);                    \
            cp_async16(prodBase + 16384 + soff[_i], pB[_i]);            \
            pA[_i] += KC; pB[_i] += KC;                                 \
        }                                                               \
        CP_COMMIT();                                                    \
        prodBase += (ps == NSTAGE - 1) ? (uint32_t)(0u - 2u * SSZ) : SSZ; \
        ps = (ps == NSTAGE - 1) ? 0 : ps + 1;                           \
    } while (0)

    // ---- consumer fragment bases (stage 0) ----
    const int pc0 = tig ^ px, pc1 = (4 + tig) ^ px;
    uint32_t aB[2], bB[2];
    aB[0] = sb + (uint32_t)(((wm * 64 + gid) * 8 + pc0) * 16);
    aB[1] = sb + (uint32_t)(((wm * 64 + gid) * 8 + pc1) * 16);
    bB[0] = sb + 16384u + (uint32_t)(((wn * 32 + gid) * 8 + pc0) * 16);
    bB[1] = sb + 16384u + (uint32_t)(((wn * 32 + gid) * 8 + pc1) * 16);
    int fs = 0;

    float acc[4][4][4];
#pragma unroll
    for (int mt = 0; mt < 4; ++mt)
#pragma unroll
        for (int nt = 0; nt < 4; ++nt)
#pragma unroll
            for (int r = 0; r < 4; ++r) acc[mt][nt][r] = 0.f;

    ISSUE();
    ISSUE();

    for (int c = 0; c < NC; ++c) {
        if (c == NC - 1) CP_WAIT0(); else CP_WAIT1();
        __syncthreads();
        if (c + 2 < NC) ISSUE();

#pragma unroll
        for (int g = 0; g < 2; ++g) {
            const uint32_t ab = aB[g], bb = bB[g];
            uint4 b0, b1, b2, b3, p0, p1, q0, q1;
            LDS4(b0, bb, "0");    LDS4(b1, bb, "1024");
            LDS4(b2, bb, "2048"); LDS4(b3, bb, "3072");
            // mt 0,1
            LDS4(p0, ab, "0");    LDS4(p1, ab, "1024");
            LDS4(q0, ab, "2048"); LDS4(q1, ab, "3072");
            mma_f16(acc[0][0], p0.x, p1.x, p0.y, p1.y, b0.x, b0.y);
            mma_f16(acc[0][1], p0.x, p1.x, p0.y, p1.y, b1.x, b1.y);
            mma_f16(acc[0][2], p0.x, p1.x, p0.y, p1.y, b2.x, b2.y);
            mma_f16(acc[0][3], p0.x, p1.x, p0.y, p1.y, b3.x, b3.y);
            mma_f16(acc[1][0], q0.x, q1.x, q0.y, q1.y, b0.x, b0.y);
            mma_f16(acc[1][1], q0.x, q1.x, q0.y, q1.y, b1.x, b1.y);
            mma_f16(acc[1][2], q0.x, q1.x, q0.y, q1.y, b2.x, b2.y);
            mma_f16(acc[1][3], q0.x, q1.x, q0.y, q1.y, b3.x, b3.y);
            mma_f16(acc[0][0], p0.z, p1.z, p0.w, p1.w, b0.z, b0.w);
            mma_f16(acc[0][1], p0.z, p1.z, p0.w, p1.w, b1.z, b1.w);
            mma_f16(acc[0][2], p0.z, p1.z, p0.w, p1.w, b2.z, b2.w);
            mma_f16(acc[0][3], p0.z, p1.z, p0.w, p1.w, b3.z, b3.w);
            mma_f16(acc[1][0], q0.z, q1.z, q0.w, q1.w, b0.z, b0.w);
            mma_f16(acc[1][1], q0.z, q1.z, q0.w, q1.w, b1.z, b1.w);
            mma_f16(acc[1][2], q0.z, q1.z, q0.w, q1.w, b2.z, b2.w);
            mma_f16(acc[1][3], q0.z, q1.z, q0.w, q1.w, b3.z, b3.w);
            // mt 2,3
            LDS4(p0, ab, "4096"); LDS4(p1, ab, "5120");
            LDS4(q0, ab, "6144"); LDS4(q1, ab, "7168");
            mma_f16(acc[2][0], p0.x, p1.x, p0.y, p1.y, b0.x, b0.y);
            mma_f16(acc[2][1], p0.x, p1.x, p0.y, p1.y, b1.x, b1.y);
            mma_f16(acc[2][2], p0.x, p1.x, p0.y, p1.y, b2.x, b2.y);
            mma_f16(acc[2][3], p0.x, p1.x, p0.y, p1.y, b3.x, b3.y);
            mma_f16(acc[3][0], q0.x, q1.x, q0.y, q1.y, b0.x, b0.y);
            mma_f16(acc[3][1], q0.x, q1.x, q0.y, q1.y, b1.x, b1.y);
            mma_f16(acc[3][2], q0.x, q1.x, q0.y, q1.y, b2.x, b2.y);
            mma_f16(acc[3][3], q0.x, q1.x, q0.y, q1.y, b3.x, b3.y);
            mma_f16(acc[2][0], p0.z, p1.z, p0.w, p1.w, b0.z, b0.w);
            mma_f16(acc[2][1], p0.z, p1.z, p0.w, p1.w, b1.z, b1.w);
            mma_f16(acc[2][2], p0.z, p1.z, p0.w, p1.w, b2.z, b2.w);
            mma_f16(acc[2][3], p0.z, p1.z, p0.w, p1.w, b3.z, b3.w);
            mma_f16(acc[3][0], q0.z, q1.z, q0.w, q1.w, b0.z, b0.w);
            mma_f16(acc[3][1], q0.z, q1.z, q0.w, q1.w, b1.z, b1.w);
            mma_f16(acc[3][2], q0.z, q1.z, q0.w, q1.w, b2.z, b2.w);
            mma_f16(acc[3][3], q0.z, q1.z, q0.w, q1.w, b3.z, b3.w);
        }
        const uint32_t fd = (fs == NSTAGE - 1) ? (uint32_t)(0u - 2u * SSZ) : SSZ;
        aB[0] += fd; aB[1] += fd; bB[0] += fd; bB[1] += fd;
        fs = (fs == NSTAGE - 1) ? 0 : fs + 1;
    }

    // ---------------- epilogue ----------------
#pragma unroll
    for (int mt = 0; mt < 4; ++mt) {
        const int row0 = m0 + wm * 64 + mt * 16 + gid;
        float r0a = 0.f, r8a = 0.f;
        if (ga.biasMode == 2) {
            r0a = ga.bias[row0]; r8a = ga.bias[row0 + 8];
        } else if (ga.biasMode == 3) {
            const float* ub = ga.bias + (size_t)z * T_;
            r0a = ub[row0]; r8a = ub[row0 + 8];
        }
#pragma unroll
        for (int nt = 0; nt < 4; ++nt) {
            const int cl = wn * 32 + nt * 8 + tig * 2;   // logical col (even)
            float c0a = 0.f, c1a = 0.f;
            if (ga.biasMode == 1) {
                c0a = ga.bias[n0 + cl]; c1a = ga.bias[n0 + cl + 1];
            } else if (ga.biasMode == 3) {
                const float* wb = ga.bias2 + (size_t)z * T_;
                c0a = wb[n0 + cl]; c1a = wb[n0 + cl + 1];
            }
            float v00, v01, v10, v11;
            if (ga.biasMode == 3) {
                v00 = (acc[mt][nt][0] + r0a + c0a) * ga.scale;
                v01 = (acc[mt][nt][1] + r0a + c1a) * ga.scale;
                v10 = (acc[mt][nt][2] + r8a + c0a) * ga.scale;
                v11 = (acc[mt][nt][3] + r8a + c1a) * ga.scale;
            } else {
                v00 = acc[mt][nt][0] * ga.scale + r0a + c0a;
                v01 = acc[mt][nt][1] * ga.scale + r0a + c1a;
                v10 = acc[mt][nt][2] * ga.scale + r8a + c0a;
                v11 = acc[mt][nt][3] * ga.scale + r8a + c1a;
            }
            if (ga.outHalf) {
                __half* hC = (__half*)ga.C + (size_t)zb * ga.sCz + (size_t)zh * ga.sCh;
                const int Cc = n0 + cl;
                const int p0i = (Cc & ~31) + tr4((Cc >> 1) & 15) * 2;
                *(__half2*)(hC + (size_t)row0 * ga.ldc + p0i) = __floats2half2_rn(v00, v01);
                *(__half2*)(hC + (size_t)(row0 + 8) * ga.ldc + p0i) = __floats2half2_rn(v10, v11);
            } else {
                float* fC = (float*)ga.C + (size_t)zb * ga.sCz + (size_t)zh * ga.sCh;
                *(float2*)(fC + (size_t)row0 * ga.ldc + n0 + cl) = make_float2(v00, v01);
                *(float2*)(fC + (size_t)(row0 + 8) * ga.ldc + n0 + cl) = make_float2(v10, v11);
            }
        }
    }
#undef ISSUE
}

// ===== fp32 -> fp16 with pair-tr4 permutation within 32-elem groups =====
__global__ __launch_bounds__(256) void half_perm(
    const float* __restrict__ in, __half* __restrict__ out, int n16)
{
    const int o4 = blockIdx.x * 256 + threadIdx.x;
    if (o4 < n16) {
        const int eg = (o4 * 8) & ~31;       // group base (elements)
        const int t = o4 & 3;
        uint4 o;
        float2 f0 = *(const float2*)(in + eg + (t + 0) * 2);
        float2 f1 = *(const float2*)(in + eg + (t + 4) * 2);
        float2 f2 = *(const float2*)(in + eg + (t + 8) * 2);
        float2 f3 = *(const float2*)(in + eg + (t + 12) * 2);
        o.x = h2u(__floats2half2_rn(f0.x, f0.y));
        o.y = h2u(__floats2half2_rn(f1.x, f1.y));
        o.z = h2u(__floats2half2_rn(f2.x, f2.y));
        o.w = h2u(__floats2half2_rn(f3.x, f3.y));
        ((uint4*)out)[o4] = o;
    }
}

// ===== Wv transpose + fp16 + k-permute: O[n][perm(k)] = h(Wv[k][n]) =====
__global__ __launch_bounds__(256) void transpose_wv(
    const float* __restrict__ W, __half* __restrict__ O)
{
    __shared__ float t[32][33];
    const int x0 = blockIdx.x * 32, y0 = blockIdx.y * 32;
    const int tx = threadIdx.x, ty = threadIdx.y;
#pragma unroll
    for (int i = 0; i < 32; i += 8)
        t[ty + i][tx] = W[(size_t)(y0 + ty + i) * ND + x0 + tx];
    __syncthreads();
    const int kp = y0 + tr4(tx >> 1) * 2 + (tx & 1);
#pragma unroll
    for (int i = 0; i < 32; i += 8)
        O[(size_t)(x0 + ty + i) * DH + kp] = __float2half_rn(t[tx][ty + i]);
}

// ===== y[h][d]=Wq[d,h*512+:]·bk_h ; z[h][d]=Wk[d,h*512+:]·bq_h ; c[h]=bq_h·bk_h
__global__ __launch_bounds__(256) void yz_kernel(
    const float* __restrict__ Wq, const float* __restrict__ Wk,
    const float* __restrict__ bq, const float* __restrict__ bk,
    float* __restrict__ y, float* __restrict__ zv, float* __restrict__ c)
{
    const int g = blockIdx.x * 256 + threadIdx.x;   // [0, 4096)
    const int h = g >> 9, d = g & 511;
    const float* wqr = Wq + (size_t)d * ND + (h << 9);
    const float* wkr = Wk + (size_t)d * ND + (h << 9);
    const float* bkr = bk + (h << 9);
    const float* bqr = bq + (h << 9);
    float sy = 0.f, sz = 0.f;
    for (int e = 0; e < 512; ++e) { sy += wqr[e] * bkr[e]; sz += wkr[e] * bqr[e]; }
    y[g] = sy; zv[g] = sz;
    if (g < H_) {
        float sc = 0.f;
        const float* a = bq + (g << 9);
        const float* b2 = bk + (g << 9);
        for (int e = 0; e < 512; ++e) sc += a[e] * b2[e];
        c[g] = sc;
    }
}

// ===== u[b,h,i]=Q[b,i,:]·y[h]+c[h] ; w[b,h,i]=V[b,i,:]·z[h] =====
__global__ __launch_bounds__(256) void uw_kernel(
    const float* __restrict__ Q, const float* __restrict__ V,
    const float* __restrict__ y, const float* __restrict__ zv,
    const float* __restrict__ c, float* __restrict__ u, float* __restrict__ w)
{
    __shared__ float sy[H_ * DH];
    const int sel = blockIdx.y;
    const float* src = sel ? V : Q;
    const float* yz  = sel ? zv : y;
    float* dst       = sel ? w : u;
    for (int i = threadIdx.x; i < H_ * DH; i += 256) sy[i] = yz[i];
    __syncthreads();
    const int warp = threadIdx.x >> 5, lane = threadIdx.x & 31;
    const int bt = blockIdx.x * 8 + warp;
    const int b = bt >> 11, i = bt & 2047;
    float acc[H_] = {};
    const float* row = src + (size_t)bt * DH;
    for (int t = 0; t < DH / 32; ++t) {
        const float qv = row[lane + 32 * t];
#pragma unroll
        for (int h = 0; h < H_; ++h) acc[h] += qv * sy[h * DH + lane + 32 * t];
    }
#pragma unroll
    for (int h = 0; h < H_; ++h) {
        float s = acc[h];
#pragma unroll
        for (int o = 16; o > 0; o >>= 1) s += __shfl_xor_sync(~0u, s, o);
        if (lane == 0)
            dst[(size_t)(b * H_ + h) * T_ + i] = s + (sel ? 0.f : c[h]);
    }
}

// ==== causal softmax IN PLACE on fp16 pair-permuted scores ====
__global__ __launch_bounds__(256) void softmax_rows(__half* __restrict__ P)
{
    const int r = blockIdx.x, z = blockIdx.y;
    uint4* row4 = (uint4*)(P + ((size_t)z * T_ + r) * T_);
    const int L = r + 1;
    const int NQ = (((r | 127) + 1)) >> 3;   // uint4 count (128-pad)
    const int tid = threadIdx.x;
    const int wid = tid >> 5, lane = tid & 31;
    __shared__ float red[8];

    float2 v[4];
    int j0[4];
    const bool act = tid < NQ;
    if (act) {
        uint4 uu = row4[tid];
        const int t = tid & 3;
        const int E = (tid * 8) & ~31;
        __half2 h0 = *(__half2*)&uu.x, h1 = *(__half2*)&uu.y;
        __half2 h2 = *(__half2*)&uu.z, h3 = *(__half2*)&uu.w;
        v[0] = __half22float2(h0); j0[0] = E + 2 * t;
        v[1] = __half22float2(h1); j0[1] = E + 8 + 2 * t;
        v[2] = __half22float2(h2); j0[2] = E + 16 + 2 * t;
        v[3] = __half22float2(h3); j0[3] = E + 24 + 2 * t;
    }

    float m = -1e30f;
    if (act) {
#pragma unroll
        for (int i = 0; i < 4; ++i) {
            if (j0[i]     < L) m = fmaxf(m, v[i].x);
            if (j0[i] + 1 < L) m = fmaxf(m, v[i].y);
        }
    }
#pragma unroll
    for (int o = 16; o > 0; o >>= 1) m = fmaxf(m, __shfl_xor_sync(~0u, m, o));
    if (lane == 0) red[wid] = m;
    __syncthreads();
    m = fmaxf(fmaxf(fmaxf(red[0], red[1]), fmaxf(red[2], red[3])),
              fmaxf(fmaxf(red[4], red[5]), fmaxf(red[6], red[7])));
    __syncthreads();

    float sum = 0.f;
    if (act) {
#pragma unroll
        for (int i = 0; i < 4; ++i) {
            v[i].x = (j0[i]     < L) ? __expf(v[i].x - m) : 0.f;
            v[i].y = (j0[i] + 1 < L) ? __expf(v[i].y - m) : 0.f;
            sum += v[i].x + v[i].y;
        }
    }
#pragma unroll
    for (int o = 16; o > 0; o >>= 1) sum += __shfl_xor_sync(~0u, sum, o);
    if (lane == 0) red[wid] = sum;
    __syncthreads();
    const float inv = 1.0f / (red[0] + red[1] + red[2] + red[3] +
                              red[4] + red[5] + red[6] + red[7]);

    if (act) {
        uint4 o;
        o.x = h2u(__floats2half2_rn(v[0].x * inv, v[0].y * inv));
        o.y = h2u(__floats2half2_rn(v[1].x * inv, v[1].y * inv));
        o.z = h2u(__floats2half2_rn(v[2].x * inv, v[2].y * inv));
        o.w = h2u(__floats2half2_rn(v[3].x * inv, v[3].y * inv));
        row4[tid] = o;
    }
}

// =====================================================================
extern "C" void kernel_launch(void* const* d_in, const int* in_sizes, int n_in,
                              void* d_out, int out_size)
{
    const float* query = (const float*)d_in[0];
    const float* value = (const float*)d_in[1];
    const float* Wq    = (const float*)d_in[2];
    const float* bq    = (const float*)d_in[3];
    const float* Wk    = (const float*)d_in[4];
    const float* bk    = (const float*)d_in[5];
    const float* Wv    = (const float*)d_in[6];
    const float* bv    = (const float*)d_in[7];
    float* out = (float*)d_out;

    __half *q, *vt, *p, *mt, *wq16, *wk16, *wvt, *qr, *vr;
    float *y, *zv, *c, *u, *w;
    cudaGetSymbolAddress((void**)&q,    g_q);
    cudaGetSymbolAddress((void**)&vt,   g_vt);
    cudaGetSymbolAddress((void**)&p,    g_p);
    cudaGetSymbolAddress((void**)&mt,   g_mt);
    cudaGetSymbolAddress((void**)&wq16, g_wq16);
    cudaGetSymbolAddress((void**)&wk16, g_wk16);
    cudaGetSymbolAddress((void**)&wvt,  g_wvt);
    cudaGetSymbolAddress((void**)&qr,   g_qr);
    cudaGetSymbolAddress((void**)&vr,   g_vr);
    cudaGetSymbolAddress((void**)&y,    g_y);
    cudaGetSymbolAddress((void**)&zv,   g_z);
    cudaGetSymbolAddress((void**)&c,    g_c);
    cudaGetSymbolAddress((void**)&u,    g_u);
    cudaGetSymbolAddress((void**)&w,    g_w);

    cudaFuncSetAttribute(gemm_tc, cudaFuncAttributeMaxDynamicSharedMemorySize, SMEM_BYTES);

    // ---- pre-passes ----
    const int nIn16 = BT * DH / 8;            // query/value
    const int nW16  = DH * ND / 8;            // Wq/Wk
    half_perm<<<nIn16 / 256, 256>>>(query, qr, nIn16);
    half_perm<<<nIn16 / 256, 256>>>(value, vr, nIn16);
    half_perm<<<nW16 / 256, 256>>>(Wq, wq16, nW16);
    half_perm<<<nW16 / 256, 256>>>(Wk, wk16, nW16);
    transpose_wv<<<dim3(ND / 32, DH / 32), dim3(32, 8)>>>(Wv, wvt);
    yz_kernel<<<16, 256>>>(Wq, Wk, bq, bk, y, zv, c);
    uw_kernel<<<dim3(BT / 8, 2), 256>>>(query, value, y, zv, c, u, w);

    GemmArgs a;

    // M-GEMM: Mt[h*512+e][d] = sum_f Wk[e, h*512+f] * Wq[d, h*512+f]
    a = { wk16, 0, 512, ND,
          wq16, 0, 512, ND,
          mt, 0, 512LL * 512, 512,
          DH, 8, nullptr, nullptr, 0, 1.0f, 0, 1 };
    gemm_tc<<<dim3(4, 4, 8), 256, SMEM_BYTES>>>(a);

    // q-hat GEMM: g_q[i][h*512+e] = sum_d qr[i][d] * Mt[h*512+e][d]
    a = { qr, 0, 0, DH,
          mt, 0, 0, DH,
          q, 0, 0, ND,
          DH, 1, nullptr, nullptr, 0, 1.0f, 0, 1 };
    gemm_tc<<<dim3(ND / TN, BT / TM, 1), 256, SMEM_BYTES>>>(a);

    // vt = Wv^T @ value^T + bv  (fp16, t-permuted out)
    a = { wvt, 0, 0, DH,
          vr, (long long)T_ * DH, 0, DH,
          vt, (long long)ND * T_, 0, T_,
          DH, 1, bv, nullptr, 2, 1.0f, 0, 1 };
    gemm_tc<<<dim3(T_ / TN, ND / TM, B_), 256, SMEM_BYTES>>>(a);

    // scores = scale*(qhat @ value^T + u + w + c)  (causal skip; fp16 perm out)
    a = { q, (long long)T_ * ND, 512, ND,
          vr, (long long)T_ * DH, 0, DH,
          p, 8LL * T_ * T_, (long long)T_ * T_, T_,
          DH, H_, u, w, 3, 0.044194173824159216f, 1, 1 };
    gemm_tc<<<dim3(T_ / TN, T_ / TM, B_ * H_), 256, SMEM_BYTES>>>(a);

    // softmax in place on fp16 permuted scores (pad to 128)
    softmax_rows<<<dim3(T_, B_ * H_), 256>>>(p);

    // out = P @ V   (K bounded at m0+128; fp32 plain out)
    a = { p, 8LL * T_ * T_, (long long)T_ * T_, T_,
          vt, (long long)ND * T_, (long long)DH * T_, T_,
          out, (long long)T_ * ND, DH, ND,
          T_, H_, nullptr, nullptr, 0, 1.0f, 2, 0 };
    gemm_tc<<<dim3(DH / TN, T_ / TM, B_ * H_), 256, SMEM_BYTES>>>(a);
}

// round 16
// speedup vs baseline: 1.1760x; 1.1760x over previous
#include <cuda_runtime.h>
#include <cuda_fp16.h>
#include <math.h>
#include <cstdint>

#define B_  4
#define T_  2048
#define DH  512
#define H_  8
#define ND  4096
#define BT  8192
#define TM  128
#define TN  128
#define KC  64                           // fp16 elems per chunk = 128B rows
#define NSTAGE 3
#define SSZ (2 * TM * 128)               // stage bytes (A 16KB + B 16KB) = 32768
#define SMEM_BYTES (NSTAGE * SSZ)        // 98304

// ---------------- scratch (device globals: allocation-free) ----------------
__device__ __half g_q  [(size_t)BT * ND];           // q-hat fp16, pair-permuted
__device__ __half g_vt [(size_t)B_ * ND * T_];      // [b][h*DH+d][t-perm] fp16
__device__ __half g_p  [(size_t)B_ * H_ * T_ * T_]; // scores->probs fp16, j-perm
__device__ __half g_mt [(size_t)ND * DH];           // Mt[h*512+e][d] fp16 perm
__device__ __half g_wq16[(size_t)DH * ND];          // Wq fp16 col-permuted
__device__ __half g_wk16[(size_t)DH * ND];          // Wk fp16 col-permuted
__device__ __half g_wvt[(size_t)ND * DH];           // Wv^T fp16 k-permuted
__device__ __half g_qr [(size_t)BT * DH];           // query fp16 k-permuted
__device__ __half g_vr [(size_t)BT * DH];           // value fp16 k-permuted
__device__ float  g_y[H_ * DH], g_z[H_ * DH], g_c[H_];   // y/z stored PERMUTED
__device__ float  g_u[(size_t)B_ * H_ * T_];        // row-bias planes (logical)
__device__ float  g_w[(size_t)B_ * H_ * T_];        // col-bias planes (logical)

__device__ __forceinline__ int tr4(int x) { return ((x & 3) << 2) | (x >> 2); }
__device__ __forceinline__ uint32_t h2u(__half2 h) {
    return *reinterpret_cast<uint32_t*>(&h);
}
__device__ __forceinline__ uint32_t smem_u32(const void* p) {
    uint32_t a;
    asm("{ .reg .u64 t; cvta.to.shared.u64 t, %1; cvt.u32.u64 %0, t; }" : "=r"(a) : "l"(p));
    return a;
}
__device__ __forceinline__ void cp_async16(uint32_t saddr, const void* gaddr) {
    asm volatile("cp.async.cg.shared.global [%0], [%1], 16;" :: "r"(saddr), "l"(gaddr));
}
#define CP_COMMIT() asm volatile("cp.async.commit_group;" ::: "memory")
#define CP_WAIT1()  asm volatile("cp.async.wait_group 1;" ::: "memory")
#define CP_WAIT0()  asm volatile("cp.async.wait_group 0;" ::: "memory")

#define LDS4(v, base, IMM) \
    asm volatile("ld.shared.v4.b32 {%0,%1,%2,%3}, [%4+" IMM "];" \
        : "=r"((v).x), "=r"((v).y), "=r"((v).z), "=r"((v).w) : "r"(base))

__device__ __forceinline__ void mma_f16(float* c,
                                        uint32_t a0, uint32_t a1, uint32_t a2, uint32_t a3,
                                        uint32_t b0, uint32_t b1) {
    asm volatile("mma.sync.aligned.m16n8k16.row.col.f32.f16.f16.f32 "
                 "{%0,%1,%2,%3}, {%4,%5,%6,%7}, {%8,%9}, {%0,%1,%2,%3};"
                 : "+f"(c[0]), "+f"(c[1]), "+f"(c[2]), "+f"(c[3])
                 : "r"(a0), "r"(a1), "r"(a2), "r"(a3), "r"(b0), "r"(b1));
}

// ======================= generic fp16 mma.sync GEMM =======================
struct GemmArgs {
    const __half* A; long long sAz, sAh; int lda;
    const __half* B; long long sBz, sBh; int ldb;
    void*         C; long long sCz, sCh; int ldc;
    int K; int zHeads;
    const float* bias; const float* bias2;
    int biasMode;     // 0 none, 1 by-col, 2 by-row, 3 row(u)+col(w) pre-scale
    float scale;
    int causal;       // 0 none, 1 skip tj>ti, 2 kmax=m0+TM
    int outHalf;      // 1: fp16 pair-permuted out, 0: fp32 plain
};

__global__ __launch_bounds__(256, 2) void gemm_tc(GemmArgs ga)
{
    const int ti = blockIdx.y, tj = blockIdx.x, z = blockIdx.z;
    if (ga.causal == 1 && tj > ti) return;

    extern __shared__ uint32_t smem[];
    const uint32_t sb = smem_u32(smem);

    const int tid  = threadIdx.x;
    const int wid  = tid >> 5, lane = tid & 31;
    const int wm   = wid >> 2, wn = wid & 3;        // 2 x 4 warp grid
    const int gid  = lane >> 2, tig = lane & 3;
    const int m0 = ti * TM, n0 = tj * TN;
    const int px = (gid & 1) << 2;

    int kmax = ga.K;
    if (ga.causal == 2) kmax = min(kmax, m0 + TM);
    const int NC = kmax / KC;

    const int zb = z / ga.zHeads, zh = z - zb * ga.zHeads;
    const __half* Ag = ga.A + (size_t)zb * ga.sAz + (size_t)zh * ga.sAh;
    const __half* Bg = ga.B + (size_t)zb * ga.sBz + (size_t)zh * ga.sBh;

    // ---- producer: rows are 8 chunks of 16B (128B pitch) ----
    int soff[4];
    const __half *pA[4], *pB[4];
#pragma unroll
    for (int i = 0; i < 4; ++i) {
        const int id = i * 256 + tid;
        const int row = id >> 3, ch = id & 7;
        soff[i] = (row * 8 + (ch ^ ((row & 1) << 2))) * 16;
        pA[i] = Ag + (size_t)(m0 + row) * ga.lda + ch * 8;
        pB[i] = Bg + (size_t)(n0 + row) * ga.ldb + ch * 8;
    }
    uint32_t prodBase = sb;
    int ps = 0;

#define ISSUE() do {                                                    \
        _Pragma("unroll")                                               \
        for (int _i = 0; _i < 4; ++_i) {                                \
            cp_async16(prodBase + soff[_i], pA[_i]);                    \
            cp_async16(prodBase + 16384 + soff[_i], pB[_i]);            \
            pA[_i] += KC; pB[_i] += KC;                                 \
        }                                                               \
        CP_COMMIT();                                                    \
        prodBase += (ps == NSTAGE - 1) ? (uint32_t)(0u - 2u * SSZ) : SSZ; \
        ps = (ps == NSTAGE - 1) ? 0 : ps + 1;                           \
    } while (0)

    // ---- consumer fragment bases (stage 0) ----
    const int pc0 = tig ^ px, pc1 = (4 + tig) ^ px;
    uint32_t aB[2], bB[2];
    aB[0] = sb + (uint32_t)(((wm * 64 + gid) * 8 + pc0) * 16);
    aB[1] = sb + (uint32_t)(((wm * 64 + gid) * 8 + pc1) * 16);
    bB[0] = sb + 16384u + (uint32_t)(((wn * 32 + gid) * 8 + pc0) * 16);
    bB[1] = sb + 16384u + (uint32_t)(((wn * 32 + gid) * 8 + pc1) * 16);
    int fs = 0;

    float acc[4][4][4];
#pragma unroll
    for (int mt = 0; mt < 4; ++mt)
#pragma unroll
        for (int nt = 0; nt < 4; ++nt)
#pragma unroll
            for (int r = 0; r < 4; ++r) acc[mt][nt][r] = 0.f;

    ISSUE();
    ISSUE();

    for (int c = 0; c < NC; ++c) {
        if (c == NC - 1) CP_WAIT0(); else CP_WAIT1();
        __syncthreads();
        if (c + 2 < NC) ISSUE();

#pragma unroll
        for (int g = 0; g < 2; ++g) {
            const uint32_t ab = aB[g], bb = bB[g];
            uint4 b0, b1, b2, b3, p0, p1, q0, q1;
            LDS4(b0, bb, "0");    LDS4(b1, bb, "1024");
            LDS4(b2, bb, "2048"); LDS4(b3, bb, "3072");
            // mt 0,1
            LDS4(p0, ab, "0");    LDS4(p1, ab, "1024");
            LDS4(q0, ab, "2048"); LDS4(q1, ab, "3072");
            mma_f16(acc[0][0], p0.x, p1.x, p0.y, p1.y, b0.x, b0.y);
            mma_f16(acc[0][1], p0.x, p1.x, p0.y, p1.y, b1.x, b1.y);
            mma_f16(acc[0][2], p0.x, p1.x, p0.y, p1.y, b2.x, b2.y);
            mma_f16(acc[0][3], p0.x, p1.x, p0.y, p1.y, b3.x, b3.y);
            mma_f16(acc[1][0], q0.x, q1.x, q0.y, q1.y, b0.x, b0.y);
            mma_f16(acc[1][1], q0.x, q1.x, q0.y, q1.y, b1.x, b1.y);
            mma_f16(acc[1][2], q0.x, q1.x, q0.y, q1.y, b2.x, b2.y);
            mma_f16(acc[1][3], q0.x, q1.x, q0.y, q1.y, b3.x, b3.y);
            mma_f16(acc[0][0], p0.z, p1.z, p0.w, p1.w, b0.z, b0.w);
            mma_f16(acc[0][1], p0.z, p1.z, p0.w, p1.w, b1.z, b1.w);
            mma_f16(acc[0][2], p0.z, p1.z, p0.w, p1.w, b2.z, b2.w);
            mma_f16(acc[0][3], p0.z, p1.z, p0.w, p1.w, b3.z, b3.w);
            mma_f16(acc[1][0], q0.z, q1.z, q0.w, q1.w, b0.z, b0.w);
            mma_f16(acc[1][1], q0.z, q1.z, q0.w, q1.w, b1.z, b1.w);
            mma_f16(acc[1][2], q0.z, q1.z, q0.w, q1.w, b2.z, b2.w);
            mma_f16(acc[1][3], q0.z, q1.z, q0.w, q1.w, b3.z, b3.w);
            // mt 2,3
            LDS4(p0, ab, "4096"); LDS4(p1, ab, "5120");
            LDS4(q0, ab, "6144"); LDS4(q1, ab, "7168");
            mma_f16(acc[2][0], p0.x, p1.x, p0.y, p1.y, b0.x, b0.y);
            mma_f16(acc[2][1], p0.x, p1.x, p0.y, p1.y, b1.x, b1.y);
            mma_f16(acc[2][2], p0.x, p1.x, p0.y, p1.y, b2.x, b2.y);
            mma_f16(acc[2][3], p0.x, p1.x, p0.y, p1.y, b3.x, b3.y);
            mma_f16(acc[3][0], q0.x, q1.x, q0.y, q1.y, b0.x, b0.y);
            mma_f16(acc[3][1], q0.x, q1.x, q0.y, q1.y, b1.x, b1.y);
            mma_f16(acc[3][2], q0.x, q1.x, q0.y, q1.y, b2.x, b2.y);
            mma_f16(acc[3][3], q0.x, q1.x, q0.y, q1.y, b3.x, b3.y);
            mma_f16(acc[2][0], p0.z, p1.z, p0.w, p1.w, b0.z, b0.w);
            mma_f16(acc[2][1], p0.z, p1.z, p0.w, p1.w, b1.z, b1.w);
            mma_f16(acc[2][2], p0.z, p1.z, p0.w, p1.w, b2.z, b2.w);
            mma_f16(acc[2][3], p0.z, p1.z, p0.w, p1.w, b3.z, b3.w);
            mma_f16(acc[3][0], q0.z, q1.z, q0.w, q1.w, b0.z, b0.w);
            mma_f16(acc[3][1], q0.z, q1.z, q0.w, q1.w, b1.z, b1.w);
            mma_f16(acc[3][2], q0.z, q1.z, q0.w, q1.w, b2.z, b2.w);
            mma_f16(acc[3][3], q0.z, q1.z, q0.w, q1.w, b3.z, b3.w);
        }
        const uint32_t fd = (fs == NSTAGE - 1) ? (uint32_t)(0u - 2u * SSZ) : SSZ;
        aB[0] += fd; aB[1] += fd; bB[0] += fd; bB[1] += fd;
        fs = (fs == NSTAGE - 1) ? 0 : fs + 1;
    }

    // ---------------- epilogue ----------------
#pragma unroll
    for (int mt = 0; mt < 4; ++mt) {
        const int row0 = m0 + wm * 64 + mt * 16 + gid;
        float r0a = 0.f, r8a = 0.f;
        if (ga.biasMode == 2) {
            r0a = ga.bias[row0]; r8a = ga.bias[row0 + 8];
        } else if (ga.biasMode == 3) {
            const float* ub = ga.bias + (size_t)z * T_;
            r0a = ub[row0]; r8a = ub[row0 + 8];
        }
#pragma unroll
        for (int nt = 0; nt < 4; ++nt) {
            const int cl = wn * 32 + nt * 8 + tig * 2;   // logical col (even)
            float c0a = 0.f, c1a = 0.f;
            if (ga.biasMode == 1) {
                c0a = ga.bias[n0 + cl]; c1a = ga.bias[n0 + cl + 1];
            } else if (ga.biasMode == 3) {
                const float* wb = ga.bias2 + (size_t)z * T_;
                c0a = wb[n0 + cl]; c1a = wb[n0 + cl + 1];
            }
            float v00, v01, v10, v11;
            if (ga.biasMode == 3) {
                v00 = (acc[mt][nt][0] + r0a + c0a) * ga.scale;
                v01 = (acc[mt][nt][1] + r0a + c1a) * ga.scale;
                v10 = (acc[mt][nt][2] + r8a + c0a) * ga.scale;
                v11 = (acc[mt][nt][3] + r8a + c1a) * ga.scale;
            } else {
                v00 = acc[mt][nt][0] * ga.scale + r0a + c0a;
                v01 = acc[mt][nt][1] * ga.scale + r0a + c1a;
                v10 = acc[mt][nt][2] * ga.scale + r8a + c0a;
                v11 = acc[mt][nt][3] * ga.scale + r8a + c1a;
            }
            if (ga.outHalf) {
                __half* hC = (__half*)ga.C + (size_t)zb * ga.sCz + (size_t)zh * ga.sCh;
                const int Cc = n0 + cl;
                const int p0i = (Cc & ~31) + tr4((Cc >> 1) & 15) * 2;
                *(__half2*)(hC + (size_t)row0 * ga.ldc + p0i) = __floats2half2_rn(v00, v01);
                *(__half2*)(hC + (size_t)(row0 + 8) * ga.ldc + p0i) = __floats2half2_rn(v10, v11);
            } else {
                float* fC = (float*)ga.C + (size_t)zb * ga.sCz + (size_t)zh * ga.sCh;
                *(float2*)(fC + (size_t)row0 * ga.ldc + n0 + cl) = make_float2(v00, v01);
                *(float2*)(fC + (size_t)(row0 + 8) * ga.ldc + n0 + cl) = make_float2(v10, v11);
            }
        }
    }
#undef ISSUE
}

// ===== fp32 -> fp16 with pair-tr4 permutation; two tensors per launch =====
__global__ __launch_bounds__(256) void half_perm2(
    const float* __restrict__ in0, __half* __restrict__ out0,
    const float* __restrict__ in1, __half* __restrict__ out1, int n16)
{
    const int o4 = blockIdx.x * 256 + threadIdx.x;
    const float* in  = blockIdx.y ? in1 : in0;
    __half* out      = blockIdx.y ? out1 : out0;
    if (o4 < n16) {
        const int eg = (o4 * 8) & ~31;
        const int t = o4 & 3;
        uint4 o;
        float2 f0 = *(const float2*)(in + eg + (t + 0) * 2);
        float2 f1 = *(const float2*)(in + eg + (t + 4) * 2);
        float2 f2 = *(const float2*)(in + eg + (t + 8) * 2);
        float2 f3 = *(const float2*)(in + eg + (t + 12) * 2);
        o.x = h2u(__floats2half2_rn(f0.x, f0.y));
        o.y = h2u(__floats2half2_rn(f1.x, f1.y));
        o.z = h2u(__floats2half2_rn(f2.x, f2.y));
        o.w = h2u(__floats2half2_rn(f3.x, f3.y));
        ((uint4*)out)[o4] = o;
    }
}

// ===== Wv transpose + fp16 + k-permute: O[n][perm(k)] = h(Wv[k][n]) =====
__global__ __launch_bounds__(256) void transpose_wv(
    const float* __restrict__ W, __half* __restrict__ O)
{
    __shared__ float t[32][33];
    const int x0 = blockIdx.x * 32, y0 = blockIdx.y * 32;
    const int tx = threadIdx.x, ty = threadIdx.y;
#pragma unroll
    for (int i = 0; i < 32; i += 8)
        t[ty + i][tx] = W[(size_t)(y0 + ty + i) * ND + x0 + tx];
    __syncthreads();
    const int kp = y0 + tr4(tx >> 1) * 2 + (tx & 1);
#pragma unroll
    for (int i = 0; i < 32; i += 8)
        O[(size_t)(x0 + ty + i) * DH + kp] = __float2half_rn(t[tx][ty + i]);
}

// ===== warp-per-output y/z/c: y,z stored in tr4-pair-PERMUTED d order =====
// y[h][d]=Wq[d,h*512+:]·bk_h ; z[h][d]=Wk[d,h*512+:]·bq_h ; c[h]=bq_h·bk_h
__global__ __launch_bounds__(256) void yz_kernel(
    const float* __restrict__ Wq, const float* __restrict__ Wk,
    const float* __restrict__ bq, const float* __restrict__ bk,
    float* __restrict__ y, float* __restrict__ zv, float* __restrict__ c)
{
    const int wg = blockIdx.x * 8 + (threadIdx.x >> 5);   // global warp id
    const int lane = threadIdx.x & 31;
    if (wg < 8192) {
        const int sel = wg >> 12;          // 0: y, 1: z
        const int g = wg & 4095;
        const int h = g >> 9, d = g & 511;
        const float* wr = (sel ? Wk : Wq) + (size_t)d * ND + (h << 9);
        const float* br = (sel ? bq : bk) + (h << 9);
        float s = 0.f;
        for (int e = lane; e < 512; e += 32) s += wr[e] * br[e];
#pragma unroll
        for (int o = 16; o > 0; o >>= 1) s += __shfl_xor_sync(~0u, s, o);
        if (lane == 0) {
            const int lp = d >> 1;
            const int sp = (lp & ~15) | tr4(lp & 15);
            const int sd = 2 * sp + (d & 1);
            (sel ? zv : y)[h * DH + sd] = s;
        }
    } else if (wg < 8192 + H_) {
        const int h = wg - 8192;
        const float* a = bq + (h << 9);
        const float* b2 = bk + (h << 9);
        float s = 0.f;
        for (int e = lane; e < 512; e += 32) s += a[e] * b2[e];
#pragma unroll
        for (int o = 16; o > 0; o >>= 1) s += __shfl_xor_sync(~0u, s, o);
        if (lane == 0) c[h] = s;
    }
}

// ===== u[b,h,i]=Q[b,i,:]·y[h]+c[h] ; w[b,h,i]=V[b,i,:]·z[h]  (fp16 inputs) =====
// qr/vr and y/z share the same d-permutation, so storage-order dots are exact.
__global__ __launch_bounds__(256) void uw_kernel(
    const __half* __restrict__ Qh, const __half* __restrict__ Vh,
    const float* __restrict__ y, const float* __restrict__ zv,
    const float* __restrict__ c, float* __restrict__ u, float* __restrict__ w)
{
    __shared__ float sy[H_ * DH];
    const int sel = blockIdx.y;
    const __half* src = sel ? Vh : Qh;
    const float* yz   = sel ? zv : y;
    float* dst        = sel ? w : u;
    for (int i = threadIdx.x; i < H_ * DH; i += 256) sy[i] = yz[i];
    __syncthreads();
    const int warp = threadIdx.x >> 5, lane = threadIdx.x & 31;
    const int bt = blockIdx.x * 8 + warp;
    const int b = bt >> 11, i = bt & 2047;
    float acc[H_] = {};
    const __half2* row = (const __half2*)(src + (size_t)bt * DH);
    for (int t = 0; t < DH / 64; ++t) {
        const int e2 = lane + 32 * t;               // half2 index (0..255)
        const float2 qv = __half22float2(row[e2]);
#pragma unroll
        for (int h = 0; h < H_; ++h) {
            acc[h] += qv.x * sy[h * DH + 2 * e2] + qv.y * sy[h * DH + 2 * e2 + 1];
        }
    }
#pragma unroll
    for (int h = 0; h < H_; ++h) {
        float s = acc[h];
#pragma unroll
        for (int o = 16; o > 0; o >>= 1) s += __shfl_xor_sync(~0u, s, o);
        if (lane == 0)
            dst[(size_t)(b * H_ + h) * T_ + i] = s + (sel ? 0.f : c[h]);
    }
}

// ==== causal softmax IN PLACE on fp16 pair-permuted scores (128 threads) ====
__global__ __launch_bounds__(128) void softmax_rows(__half* __restrict__ P)
{
    const int r = blockIdx.x, z = blockIdx.y;
    uint4* row4 = (uint4*)(P + ((size_t)z * T_ + r) * T_);
    const int L = r + 1;
    const int NQ = (((r | 127) + 1)) >> 3;   // uint4 count (128-pad), <= 256
    const int tid = threadIdx.x;             // 0..127
    const int wid = tid >> 5, lane = tid & 31;
    __shared__ float red[4];

    float2 v[2][4];
    int act[2];
    float m = -1e30f;
#pragma unroll
    for (int s = 0; s < 2; ++s) {
        const int q = tid + s * 128;
        act[s] = (q < NQ);
        if (act[s]) {
            uint4 uu = row4[q];
            const int t = q & 3;
            const int E = (q * 8) & ~31;
            v[s][0] = __half22float2(*(__half2*)&uu.x);
            v[s][1] = __half22float2(*(__half2*)&uu.y);
            v[s][2] = __half22float2(*(__half2*)&uu.z);
            v[s][3] = __half22float2(*(__half2*)&uu.w);
#pragma unroll
            for (int i = 0; i < 4; ++i) {
                const int j0 = E + 8 * i + 2 * t;
                if (j0     < L) m = fmaxf(m, v[s][i].x);
                if (j0 + 1 < L) m = fmaxf(m, v[s][i].y);
            }
        }
    }
#pragma unroll
    for (int o = 16; o > 0; o >>= 1) m = fmaxf(m, __shfl_xor_sync(~0u, m, o));
    if (lane == 0) red[wid] = m;
    __syncthreads();
    m = fmaxf(fmaxf(red[0], red[1]), fmaxf(red[2], red[3]));
    __syncthreads();

    float sum = 0.f;
#pragma unroll
    for (int s = 0; s < 2; ++s) {
        if (act[s]) {
            const int q = tid + s * 128;
            const int t = q & 3;
            const int E = (q * 8) & ~31;
#pragma unroll
            for (int i = 0; i < 4; ++i) {
                const int j0 = E + 8 * i + 2 * t;
                v[s][i].x = (j0     < L) ? __expf(v[s][i].x - m) : 0.f;
                v[s][i].y = (j0 + 1 < L) ? __expf(v[s][i].y - m) : 0.f;
                sum += v[s][i].x + v[s][i].y;
            }
        }
    }
#pragma unroll
    for (int o = 16; o > 0; o >>= 1) sum += __shfl_xor_sync(~0u, sum, o);
    if (lane == 0) red[wid] = sum;
    __syncthreads();
    const float inv = 1.0f / (red[0] + red[1] + red[2] + red[3]);

#pragma unroll
    for (int s = 0; s < 2; ++s) {
        if (act[s]) {
            uint4 o;
            o.x = h2u(__floats2half2_rn(v[s][0].x * inv, v[s][0].y * inv));
            o.y = h2u(__floats2half2_rn(v[s][1].x * inv, v[s][1].y * inv));
            o.z = h2u(__floats2half2_rn(v[s][2].x * inv, v[s][2].y * inv));
            o.w = h2u(__floats2half2_rn(v[s][3].x * inv, v[s][3].y * inv));
            row4[tid + s * 128] = o;
        }
    }
}

// =====================================================================
extern "C" void kernel_launch(void* const* d_in, const int* in_sizes, int n_in,
                              void* d_out, int out_size)
{
    const float* query = (const float*)d_in[0];
    const float* value = (const float*)d_in[1];
    const float* Wq    = (const float*)d_in[2];
    const float* bq    = (const float*)d_in[3];
    const float* Wk    = (const float*)d_in[4];
    const float* bk    = (const float*)d_in[5];
    const float* Wv    = (const float*)d_in[6];
    const float* bv    = (const float*)d_in[7];
    float* out = (float*)d_out;

    __half *q, *vt, *p, *mt, *wq16, *wk16, *wvt, *qr, *vr;
    float *y, *zv, *c, *u, *w;
    cudaGetSymbolAddress((void**)&q,    g_q);
    cudaGetSymbolAddress((void**)&vt,   g_vt);
    cudaGetSymbolAddress((void**)&p,    g_p);
    cudaGetSymbolAddress((void**)&mt,   g_mt);
    cudaGetSymbolAddress((void**)&wq16, g_wq16);
    cudaGetSymbolAddress((void**)&wk16, g_wk16);
    cudaGetSymbolAddress((void**)&wvt,  g_wvt);
    cudaGetSymbolAddress((void**)&qr,   g_qr);
    cudaGetSymbolAddress((void**)&vr,   g_vr);
    cudaGetSymbolAddress((void**)&y,    g_y);
    cudaGetSymbolAddress((void**)&zv,   g_z);
    cudaGetSymbolAddress((void**)&c,    g_c);
    cudaGetSymbolAddress((void**)&u,    g_u);
    cudaGetSymbolAddress((void**)&w,    g_w);

    cudaFuncSetAttribute(gemm_tc, cudaFuncAttributeMaxDynamicSharedMemorySize, SMEM_BYTES);

    // ---- pre-passes ----
    const int nIn16 = BT * DH / 8;            // query/value
    const int nW16  = DH * ND / 8;            // Wq/Wk
    half_perm2<<<dim3(nIn16 / 256, 2), 256>>>(query, qr, value, vr, nIn16);
    half_perm2<<<dim3(nW16 / 256, 2), 256>>>(Wq, wq16, Wk, wk16, nW16);
    transpose_wv<<<dim3(ND / 32, DH / 32), dim3(32, 8)>>>(Wv, wvt);
    yz_kernel<<<1025, 256>>>(Wq, Wk, bq, bk, y, zv, c);
    uw_kernel<<<dim3(BT / 8, 2), 256>>>(qr, vr, y, zv, c, u, w);

    GemmArgs a;

    // M-GEMM: Mt[h*512+e][d] = sum_f Wk[e, h*512+f] * Wq[d, h*512+f]
    a = { wk16, 0, 512, ND,
          wq16, 0, 512, ND,
          mt, 0, 512LL * 512, 512,
          DH, 8, nullptr, nullptr, 0, 1.0f, 0, 1 };
    gemm_tc<<<dim3(4, 4, 8), 256, SMEM_BYTES>>>(a);

    // q-hat GEMM: g_q[i][h*512+e] = sum_d qr[i][d] * Mt[h*512+e][d]
    a = { qr, 0, 0, DH,
          mt, 0, 0, DH,
          q, 0, 0, ND,
          DH, 1, nullptr, nullptr, 0, 1.0f, 0, 1 };
    gemm_tc<<<dim3(ND / TN, BT / TM, 1), 256, SMEM_BYTES>>>(a);

    // vt = Wv^T @ value^T + bv  (fp16, t-permuted out)
    a = { wvt, 0, 0, DH,
          vr, (long long)T_ * DH, 0, DH,
          vt, (long long)ND * T_, 0, T_,
          DH, 1, bv, nullptr, 2, 1.0f, 0, 1 };
    gemm_tc<<<dim3(T_ / TN, ND / TM, B_), 256, SMEM_BYTES>>>(a);

    // scores = scale*(qhat @ value^T + u + w + c)  (causal skip; fp16 perm out)
    a = { q, (long long)T_ * ND, 512, ND,
          vr, (long long)T_ * DH, 0, DH,
          p, 8LL * T_ * T_, (long long)T_ * T_, T_,
          DH, H_, u, w, 3, 0.044194173824159216f, 1, 1 };
    gemm_tc<<<dim3(T_ / TN, T_ / TM, B_ * H_), 256, SMEM_BYTES>>>(a);

    // softmax in place on fp16 permuted scores (pad to 128)
    softmax_rows<<<dim3(T_, B_ * H_), 128>>>(p);

    // out = P @ V   (K bounded at m0+128; fp32 plain out)
    a = { p, 8LL * T_ * T_, (long long)T_ * T_, T_,
          vt, (long long)ND * T_, (long long)DH * T_, T_,
          out, (long long)T_ * ND, DH, ND,
          T_, H_, nullptr, nullptr, 0, 1.0f, 2, 0 };
    gemm_tc<<<dim3(DH / TN, T_ / TM, B_ * H_), 256, SMEM_BYTES>>>(a);
}

// round 17
// speedup vs baseline: 1.2024x; 1.0225x over previous
#include <cuda_runtime.h>
#include <cuda_fp16.h>
#include <math.h>
#include <cstdint>

#define B_  4
#define T_  2048
#define DH  512
#define H_  8
#define ND  4096
#define BT  8192
#define TM  128
#define TN  128
#define KC  64                           // fp16 elems per chunk = 128B rows
#define NSTAGE 3
#define SSZ (2 * TM * 128)               // stage bytes (A 16KB + B 16KB) = 32768
#define SMEM_BYTES (NSTAGE * SSZ)        // 98304

// ---------------- scratch (device globals: allocation-free) ----------------
__device__ __half g_q  [(size_t)BT * ND];           // q-hat fp16, pair-permuted
__device__ __half g_vt [(size_t)B_ * ND * T_];      // [b][h*DH+d][t-perm] fp16
__device__ __half g_p  [(size_t)B_ * H_ * T_ * T_]; // scores->probs fp16, j-perm
__device__ __half g_mt [(size_t)ND * DH];           // Mt[h*512+e][d] fp16 perm
__device__ __half g_wq16[(size_t)DH * ND];          // Wq fp16 col-permuted
__device__ __half g_wk16[(size_t)DH * ND];          // Wk fp16 col-permuted
__device__ __half g_wvt[(size_t)ND * DH];           // Wv^T fp16 k-permuted
__device__ __half g_qr [(size_t)BT * DH];           // query fp16 k-permuted
__device__ __half g_vr [(size_t)BT * DH];           // value fp16 k-permuted
__device__ float  g_y[H_ * DH], g_z[H_ * DH], g_c[H_];   // y/z stored PERMUTED
__device__ float  g_u[(size_t)B_ * H_ * T_];        // row-bias planes (logical)
__device__ float  g_w[(size_t)B_ * H_ * T_];        // col-bias planes (logical)

__device__ __forceinline__ int tr4(int x) { return ((x & 3) << 2) | (x >> 2); }
__device__ __forceinline__ uint32_t h2u(__half2 h) {
    return *reinterpret_cast<uint32_t*>(&h);
}
__device__ __forceinline__ uint32_t smem_u32(const void* p) {
    uint32_t a;
    asm("{ .reg .u64 t; cvta.to.shared.u64 t, %1; cvt.u32.u64 %0, t; }" : "=r"(a) : "l"(p));
    return a;
}
__device__ __forceinline__ void cp_async16(uint32_t saddr, const void* gaddr) {
    asm volatile("cp.async.cg.shared.global [%0], [%1], 16;" :: "r"(saddr), "l"(gaddr));
}
#define CP_COMMIT() asm volatile("cp.async.commit_group;" ::: "memory")
#define CP_WAIT1()  asm volatile("cp.async.wait_group 1;" ::: "memory")
#define CP_WAIT0()  asm volatile("cp.async.wait_group 0;" ::: "memory")

#define LDS4(v, base, IMM) \
    asm volatile("ld.shared.v4.b32 {%0,%1,%2,%3}, [%4+" IMM "];" \
        : "=r"((v).x), "=r"((v).y), "=r"((v).z), "=r"((v).w) : "r"(base))

__device__ __forceinline__ void mma_f16(float* c,
                                        uint32_t a0, uint32_t a1, uint32_t a2, uint32_t a3,
                                        uint32_t b0, uint32_t b1) {
    asm volatile("mma.sync.aligned.m16n8k16.row.col.f32.f16.f16.f32 "
                 "{%0,%1,%2,%3}, {%4,%5,%6,%7}, {%8,%9}, {%0,%1,%2,%3};"
                 : "+f"(c[0]), "+f"(c[1]), "+f"(c[2]), "+f"(c[3])
                 : "r"(a0), "r"(a1), "r"(a2), "r"(a3), "r"(b0), "r"(b1));
}

// ======================= generic fp16 mma.sync GEMM =======================
struct GemmArgs {
    const __half* A; long long sAz, sAh; int lda;
    const __half* B; long long sBz, sBh; int ldb;
    void*         C; long long sCz, sCh; int ldc;
    int K; int zHeads;
    const float* bias; const float* bias2;
    int biasMode;     // 0 none, 1 by-col, 2 by-row, 3 row(u)+col(w) pre-scale
    float scale;
    int causal;       // 0 none, 1 skip tj>ti, 2 kmax=m0+TM
    int outHalf;      // 1: fp16 pair-permuted out, 0: fp32 plain
};

__global__ __launch_bounds__(256, 2) void gemm_tc(GemmArgs ga)
{
    const int ti = blockIdx.y, tj = blockIdx.x, z = blockIdx.z;
    if (ga.causal == 1 && tj > ti) return;

    extern __shared__ uint32_t smem[];
    const uint32_t sb = smem_u32(smem);

    const int tid  = threadIdx.x;
    const int wid  = tid >> 5, lane = tid & 31;
    const int wm   = wid >> 2, wn = wid & 3;        // 2 x 4 warp grid
    const int gid  = lane >> 2, tig = lane & 3;
    const int m0 = ti * TM, n0 = tj * TN;
    const int px = (gid & 1) << 2;

    int kmax = ga.K;
    if (ga.causal == 2) kmax = min(kmax, m0 + TM);
    const int NC = kmax / KC;

    const int zb = z / ga.zHeads, zh = z - zb * ga.zHeads;
    const __half* Ag = ga.A + (size_t)zb * ga.sAz + (size_t)zh * ga.sAh;
    const __half* Bg = ga.B + (size_t)zb * ga.sBz + (size_t)zh * ga.sBh;

    // ---- producer: rows are 8 chunks of 16B (128B pitch) ----
    int soff[4];
    const __half *pA[4], *pB[4];
#pragma unroll
    for (int i = 0; i < 4; ++i) {
        const int id = i * 256 + tid;
        const int row = id >> 3, ch = id & 7;
        soff[i] = (row * 8 + (ch ^ ((row & 1) << 2))) * 16;
        pA[i] = Ag + (size_t)(m0 + row) * ga.lda + ch * 8;
        pB[i] = Bg + (size_t)(n0 + row) * ga.ldb + ch * 8;
    }
    uint32_t prodBase = sb;
    int ps = 0;

#define ISSUE() do {                                                    \
        _Pragma("unroll")                                               \
        for (int _i = 0; _i < 4; ++_i) {                                \
            cp_async16(prodBase + soff[_i], pA[_i]);                    \
            cp_async16(prodBase + 16384 + soff[_i], pB[_i]);            \
            pA[_i] += KC; pB[_i] += KC;                                 \
        }                                                               \
        CP_COMMIT();                                                    \
        prodBase += (ps == NSTAGE - 1) ? (uint32_t)(0u - 2u * SSZ) : SSZ; \
        ps = (ps == NSTAGE - 1) ? 0 : ps + 1;                           \
    } while (0)

    // ---- consumer fragment bases (stage 0) ----
    const int pc0 = tig ^ px, pc1 = (4 + tig) ^ px;
    uint32_t aB[2], bB[2];
    aB[0] = sb + (uint32_t)(((wm * 64 + gid) * 8 + pc0) * 16);
    aB[1] = sb + (uint32_t)(((wm * 64 + gid) * 8 + pc1) * 16);
    bB[0] = sb + 16384u + (uint32_t)(((wn * 32 + gid) * 8 + pc0) * 16);
    bB[1] = sb + 16384u + (uint32_t)(((wn * 32 + gid) * 8 + pc1) * 16);
    int fs = 0;

    float acc[4][4][4];
#pragma unroll
    for (int mt = 0; mt < 4; ++mt)
#pragma unroll
        for (int nt = 0; nt < 4; ++nt)
#pragma unroll
            for (int r = 0; r < 4; ++r) acc[mt][nt][r] = 0.f;

    ISSUE();
    ISSUE();

    for (int c = 0; c < NC; ++c) {
        if (c == NC - 1) CP_WAIT0(); else CP_WAIT1();
        __syncthreads();
        if (c + 2 < NC) ISSUE();

#pragma unroll
        for (int g = 0; g < 2; ++g) {
            const uint32_t ab = aB[g], bb = bB[g];
            uint4 b0, b1, b2, b3, p0, p1, q0, q1;
            LDS4(b0, bb, "0");    LDS4(b1, bb, "1024");
            LDS4(b2, bb, "2048"); LDS4(b3, bb, "3072");
            // mt 0,1
            LDS4(p0, ab, "0");    LDS4(p1, ab, "1024");
            LDS4(q0, ab, "2048"); LDS4(q1, ab, "3072");
            mma_f16(acc[0][0], p0.x, p1.x, p0.y, p1.y, b0.x, b0.y);
            mma_f16(acc[0][1], p0.x, p1.x, p0.y, p1.y, b1.x, b1.y);
            mma_f16(acc[0][2], p0.x, p1.x, p0.y, p1.y, b2.x, b2.y);
            mma_f16(acc[0][3], p0.x, p1.x, p0.y, p1.y, b3.x, b3.y);
            mma_f16(acc[1][0], q0.x, q1.x, q0.y, q1.y, b0.x, b0.y);
            mma_f16(acc[1][1], q0.x, q1.x, q0.y, q1.y, b1.x, b1.y);
            mma_f16(acc[1][2], q0.x, q1.x, q0.y, q1.y, b2.x, b2.y);
            mma_f16(acc[1][3], q0.x, q1.x, q0.y, q1.y, b3.x, b3.y);
            mma_f16(acc[0][0], p0.z, p1.z, p0.w, p1.w, b0.z, b0.w);
            mma_f16(acc[0][1], p0.z, p1.z, p0.w, p1.w, b1.z, b1.w);
            mma_f16(acc[0][2], p0.z, p1.z, p0.w, p1.w, b2.z, b2.w);
            mma_f16(acc[0][3], p0.z, p1.z, p0.w, p1.w, b3.z, b3.w);
            mma_f16(acc[1][0], q0.z, q1.z, q0.w, q1.w, b0.z, b0.w);
            mma_f16(acc[1][1], q0.z, q1.z, q0.w, q1.w, b1.z, b1.w);
            mma_f16(acc[1][2], q0.z, q1.z, q0.w, q1.w, b2.z, b2.w);
            mma_f16(acc[1][3], q0.z, q1.z, q0.w, q1.w, b3.z, b3.w);
            // mt 2,3
            LDS4(p0, ab, "4096"); LDS4(p1, ab, "5120");
            LDS4(q0, ab, "6144"); LDS4(q1, ab, "7168");
            mma_f16(acc[2][0], p0.x, p1.x, p0.y, p1.y, b0.x, b0.y);
            mma_f16(acc[2][1], p0.x, p1.x, p0.y, p1.y, b1.x, b1.y);
            mma_f16(acc[2][2], p0.x, p1.x, p0.y, p1.y, b2.x, b2.y);
            mma_f16(acc[2][3], p0.x, p1.x, p0.y, p1.y, b3.x, b3.y);
            mma_f16(acc[3][0], q0.x, q1.x, q0.y, q1.y, b0.x, b0.y);
            mma_f16(acc[3][1], q0.x, q1.x, q0.y, q1.y, b1.x, b1.y);
            mma_f16(acc[3][2], q0.x, q1.x, q0.y, q1.y, b2.x, b2.y);
            mma_f16(acc[3][3], q0.x, q1.x, q0.y, q1.y, b3.x, b3.y);
            mma_f16(acc[2][0], p0.z, p1.z, p0.w, p1.w, b0.z, b0.w);
            mma_f16(acc[2][1], p0.z, p1.z, p0.w, p1.w, b1.z, b1.w);
            mma_f16(acc[2][2], p0.z, p1.z, p0.w, p1.w, b2.z, b2.w);
            mma_f16(acc[2][3], p0.z, p1.z, p0.w, p1.w, b3.z, b3.w);
            mma_f16(acc[3][0], q0.z, q1.z, q0.w, q1.w, b0.z, b0.w);
            mma_f16(acc[3][1], q0.z, q1.z, q0.w, q1.w, b1.z, b1.w);
            mma_f16(acc[3][2], q0.z, q1.z, q0.w, q1.w, b2.z, b2.w);
            mma_f16(acc[3][3], q0.z, q1.z, q0.w, q1.w, b3.z, b3.w);
        }
        const uint32_t fd = (fs == NSTAGE - 1) ? (uint32_t)(0u - 2u * SSZ) : SSZ;
        aB[0] += fd; aB[1] += fd; bB[0] += fd; bB[1] += fd;
        fs = (fs == NSTAGE - 1) ? 0 : fs + 1;
    }

    // ---------------- epilogue ----------------
#pragma unroll
    for (int mt = 0; mt < 4; ++mt) {
        const int row0 = m0 + wm * 64 + mt * 16 + gid;
        float r0a = 0.f, r8a = 0.f;
        if (ga.biasMode == 2) {
            r0a = ga.bias[row0]; r8a = ga.bias[row0 + 8];
        } else if (ga.biasMode == 3) {
            const float* ub = ga.bias + (size_t)z * T_;
            r0a = ub[row0]; r8a = ub[row0 + 8];
        }
#pragma unroll
        for (int nt = 0; nt < 4; ++nt) {
            const int cl = wn * 32 + nt * 8 + tig * 2;   // logical col (even)
            float c0a = 0.f, c1a = 0.f;
            if (ga.biasMode == 1) {
                c0a = ga.bias[n0 + cl]; c1a = ga.bias[n0 + cl + 1];
            } else if (ga.biasMode == 3) {
                const float* wb = ga.bias2 + (size_t)z * T_;
                c0a = wb[n0 + cl]; c1a = wb[n0 + cl + 1];
            }
            float v00, v01, v10, v11;
            if (ga.biasMode == 3) {
                v00 = (acc[mt][nt][0] + r0a + c0a) * ga.scale;
                v01 = (acc[mt][nt][1] + r0a + c1a) * ga.scale;
                v10 = (acc[mt][nt][2] + r8a + c0a) * ga.scale;
                v11 = (acc[mt][nt][3] + r8a + c1a) * ga.scale;
            } else {
                v00 = acc[mt][nt][0] * ga.scale + r0a + c0a;
                v01 = acc[mt][nt][1] * ga.scale + r0a + c1a;
                v10 = acc[mt][nt][2] * ga.scale + r8a + c0a;
                v11 = acc[mt][nt][3] * ga.scale + r8a + c1a;
            }
            if (ga.outHalf) {
                __half* hC = (__half*)ga.C + (size_t)zb * ga.sCz + (size_t)zh * ga.sCh;
                const int Cc = n0 + cl;
                const int p0i = (Cc & ~31) + tr4((Cc >> 1) & 15) * 2;
                *(__half2*)(hC + (size_t)row0 * ga.ldc + p0i) = __floats2half2_rn(v00, v01);
                *(__half2*)(hC + (size_t)(row0 + 8) * ga.ldc + p0i) = __floats2half2_rn(v10, v11);
            } else {
                float* fC = (float*)ga.C + (size_t)zb * ga.sCz + (size_t)zh * ga.sCh;
                *(float2*)(fC + (size_t)row0 * ga.ldc + n0 + cl) = make_float2(v00, v01);
                *(float2*)(fC + (size_t)(row0 + 8) * ga.ldc + n0 + cl) = make_float2(v10, v11);
            }
        }
    }
#undef ISSUE
}

// ===== fp32 -> fp16 with pair-tr4 permutation; two tensors per launch =====
__global__ __launch_bounds__(256) void half_perm2(
    const float* __restrict__ in0, __half* __restrict__ out0,
    const float* __restrict__ in1, __half* __restrict__ out1, int n16)
{
    const int o4 = blockIdx.x * 256 + threadIdx.x;
    const float* in  = blockIdx.y ? in1 : in0;
    __half* out      = blockIdx.y ? out1 : out0;
    if (o4 < n16) {
        const int eg = (o4 * 8) & ~31;
        const int t = o4 & 3;
        uint4 o;
        float2 f0 = *(const float2*)(in + eg + (t + 0) * 2);
        float2 f1 = *(const float2*)(in + eg + (t + 4) * 2);
        float2 f2 = *(const float2*)(in + eg + (t + 8) * 2);
        float2 f3 = *(const float2*)(in + eg + (t + 12) * 2);
        o.x = h2u(__floats2half2_rn(f0.x, f0.y));
        o.y = h2u(__floats2half2_rn(f1.x, f1.y));
        o.z = h2u(__floats2half2_rn(f2.x, f2.y));
        o.w = h2u(__floats2half2_rn(f3.x, f3.y));
        ((uint4*)out)[o4] = o;
    }
}

// ===== Wv transpose + fp16 + k-permute: O[n][perm(k)] = h(Wv[k][n]) =====
__global__ __launch_bounds__(256) void transpose_wv(
    const float* __restrict__ W, __half* __restrict__ O)
{
    __shared__ float t[32][33];
    const int x0 = blockIdx.x * 32, y0 = blockIdx.y * 32;
    const int tx = threadIdx.x, ty = threadIdx.y;
#pragma unroll
    for (int i = 0; i < 32; i += 8)
        t[ty + i][tx] = W[(size_t)(y0 + ty + i) * ND + x0 + tx];
    __syncthreads();
    const int kp = y0 + tr4(tx >> 1) * 2 + (tx & 1);
#pragma unroll
    for (int i = 0; i < 32; i += 8)
        O[(size_t)(x0 + ty + i) * DH + kp] = __float2half_rn(t[tx][ty + i]);
}

// ===== warp-per-output y/z/c: y,z stored in tr4-pair-PERMUTED d order =====
__global__ __launch_bounds__(256) void yz_kernel(
    const float* __restrict__ Wq, const float* __restrict__ Wk,
    const float* __restrict__ bq, const float* __restrict__ bk,
    float* __restrict__ y, float* __restrict__ zv, float* __restrict__ c)
{
    const int wg = blockIdx.x * 8 + (threadIdx.x >> 5);   // global warp id
    const int lane = threadIdx.x & 31;
    if (wg < 8192) {
        const int sel = wg >> 12;          // 0: y, 1: z
        const int g = wg & 4095;
        const int h = g >> 9, d = g & 511;
        const float* wr = (sel ? Wk : Wq) + (size_t)d * ND + (h << 9);
        const float* br = (sel ? bq : bk) + (h << 9);
        float s = 0.f;
        for (int e = lane; e < 512; e += 32) s += wr[e] * br[e];
#pragma unroll
        for (int o = 16; o > 0; o >>= 1) s += __shfl_xor_sync(~0u, s, o);
        if (lane == 0) {
            const int lp = d >> 1;
            const int sp = (lp & ~15) | tr4(lp & 15);
            const int sd = 2 * sp + (d & 1);
            (sel ? zv : y)[h * DH + sd] = s;
        }
    } else if (wg < 8192 + H_) {
        const int h = wg - 8192;
        const float* a = bq + (h << 9);
        const float* b2 = bk + (h << 9);
        float s = 0.f;
        for (int e = lane; e < 512; e += 32) s += a[e] * b2[e];
#pragma unroll
        for (int o = 16; o > 0; o >>= 1) s += __shfl_xor_sync(~0u, s, o);
        if (lane == 0) c[h] = s;
    }
}

// ===== u[b,h,i]=Q[b,i,:]·y[h]+c[h] ; w[b,h,i]=V[b,i,:]·z[h]  (fp16 inputs) =====
__global__ __launch_bounds__(256) void uw_kernel(
    const __half* __restrict__ Qh, const __half* __restrict__ Vh,
    const float* __restrict__ y, const float* __restrict__ zv,
    const float* __restrict__ c, float* __restrict__ u, float* __restrict__ w)
{
    __shared__ float sy[H_ * DH];
    const int sel = blockIdx.y;
    const __half* src = sel ? Vh : Qh;
    const float* yz   = sel ? zv : y;
    float* dst        = sel ? w : u;
    for (int i = threadIdx.x; i < H_ * DH; i += 256) sy[i] = yz[i];
    __syncthreads();
    const int warp = threadIdx.x >> 5, lane = threadIdx.x & 31;
    const int bt = blockIdx.x * 8 + warp;
    const int b = bt >> 11, i = bt & 2047;
    float acc[H_] = {};
    const __half2* row = (const __half2*)(src + (size_t)bt * DH);
    for (int t = 0; t < DH / 64; ++t) {
        const int e2 = lane + 32 * t;               // half2 index (0..255)
        const float2 qv = __half22float2(row[e2]);
#pragma unroll
        for (int h = 0; h < H_; ++h) {
            acc[h] += qv.x * sy[h * DH + 2 * e2] + qv.y * sy[h * DH + 2 * e2 + 1];
        }
    }
#pragma unroll
    for (int h = 0; h < H_; ++h) {
        float s = acc[h];
#pragma unroll
        for (int o = 16; o > 0; o >>= 1) s += __shfl_xor_sync(~0u, s, o);
        if (lane == 0)
            dst[(size_t)(b * H_ + h) * T_ + i] = s + (sel ? 0.f : c[h]);
    }
}

// ==== causal softmax IN PLACE on fp16 pair-permuted scores (128 threads) ====
__global__ __launch_bounds__(128) void softmax_rows(__half* __restrict__ P)
{
    const int r = blockIdx.x, z = blockIdx.y;
    uint4* row4 = (uint4*)(P + ((size_t)z * T_ + r) * T_);
    const int L = r + 1;
    const int NQ = (((r | 127) + 1)) >> 3;   // uint4 count (128-pad), <= 256
    const int tid = threadIdx.x;             // 0..127
    const int wid = tid >> 5, lane = tid & 31;
    __shared__ float red[4];

    float2 v[2][4];
    int act[2];
    float m = -1e30f;
#pragma unroll
    for (int s = 0; s < 2; ++s) {
        const int q = tid + s * 128;
        act[s] = (q < NQ);
        if (act[s]) {
            uint4 uu = row4[q];
            const int t = q & 3;
            const int E = (q * 8) & ~31;
            v[s][0] = __half22float2(*(__half2*)&uu.x);
            v[s][1] = __half22float2(*(__half2*)&uu.y);
            v[s][2] = __half22float2(*(__half2*)&uu.z);
            v[s][3] = __half22float2(*(__half2*)&uu.w);
#pragma unroll
            for (int i = 0; i < 4; ++i) {
                const int j0 = E + 8 * i + 2 * t;
                if (j0     < L) m = fmaxf(m, v[s][i].x);
                if (j0 + 1 < L) m = fmaxf(m, v[s][i].y);
            }
        }
    }
#pragma unroll
    for (int o = 16; o > 0; o >>= 1) m = fmaxf(m, __shfl_xor_sync(~0u, m, o));
    if (lane == 0) red[wid] = m;
    __syncthreads();
    m = fmaxf(fmaxf(red[0], red[1]), fmaxf(red[2], red[3]));
    __syncthreads();

    float sum = 0.f;
#pragma unroll
    for (int s = 0; s < 2; ++s) {
        if (act[s]) {
            const int q = tid + s * 128;
            const int t = q & 3;
            const int E = (q * 8) & ~31;
#pragma unroll
            for (int i = 0; i < 4; ++i) {
                const int j0 = E + 8 * i + 2 * t;
                v[s][i].x = (j0     < L) ? __expf(v[s][i].x - m) : 0.f;
                v[s][i].y = (j0 + 1 < L) ? __expf(v[s][i].y - m) : 0.f;
                sum += v[s][i].x + v[s][i].y;
            }
        }
    }
#pragma unroll
    for (int o = 16; o > 0; o >>= 1) sum += __shfl_xor_sync(~0u, sum, o);
    if (lane == 0) red[wid] = sum;
    __syncthreads();
    const float inv = 1.0f / (red[0] + red[1] + red[2] + red[3]);

#pragma unroll
    for (int s = 0; s < 2; ++s) {
        if (act[s]) {
            uint4 o;
            o.x = h2u(__floats2half2_rn(v[s][0].x * inv, v[s][0].y * inv));
            o.y = h2u(__floats2half2_rn(v[s][1].x * inv, v[s][1].y * inv));
            o.z = h2u(__floats2half2_rn(v[s][2].x * inv, v[s][2].y * inv));
            o.w = h2u(__floats2half2_rn(v[s][3].x * inv, v[s][3].y * inv));
            row4[tid + s * 128] = o;
        }
    }
}

// =====================================================================
extern "C" void kernel_launch(void* const* d_in, const int* in_sizes, int n_in,
                              void* d_out, int out_size)
{
    const float* query = (const float*)d_in[0];
    const float* value = (const float*)d_in[1];
    const float* Wq    = (const float*)d_in[2];
    const float* bq    = (const float*)d_in[3];
    const float* Wk    = (const float*)d_in[4];
    const float* bk    = (const float*)d_in[5];
    const float* Wv    = (const float*)d_in[6];
    const float* bv    = (const float*)d_in[7];
    float* out = (float*)d_out;

    __half *q, *vt, *p, *mt, *wq16, *wk16, *wvt, *qr, *vr;
    float *y, *zv, *c, *u, *w;
    cudaGetSymbolAddress((void**)&q,    g_q);
    cudaGetSymbolAddress((void**)&vt,   g_vt);
    cudaGetSymbolAddress((void**)&p,    g_p);
    cudaGetSymbolAddress((void**)&mt,   g_mt);
    cudaGetSymbolAddress((void**)&wq16, g_wq16);
    cudaGetSymbolAddress((void**)&wk16, g_wk16);
    cudaGetSymbolAddress((void**)&wvt,  g_wvt);
    cudaGetSymbolAddress((void**)&qr,   g_qr);
    cudaGetSymbolAddress((void**)&vr,   g_vr);
    cudaGetSymbolAddress((void**)&y,    g_y);
    cudaGetSymbolAddress((void**)&zv,   g_z);
    cudaGetSymbolAddress((void**)&c,    g_c);
    cudaGetSymbolAddress((void**)&u,    g_u);
    cudaGetSymbolAddress((void**)&w,    g_w);

    cudaFuncSetAttribute(gemm_tc, cudaFuncAttributeMaxDynamicSharedMemorySize, SMEM_BYTES);

    // ---- fork a side stream for the independent branch ----
    cudaStream_t s2;
    cudaStreamCreateWithFlags(&s2, cudaStreamNonBlocking);
    cudaEvent_t evIn, evPre, evScores, evVt;
    cudaEventCreateWithFlags(&evIn,     cudaEventDisableTiming);
    cudaEventCreateWithFlags(&evPre,    cudaEventDisableTiming);
    cudaEventCreateWithFlags(&evScores, cudaEventDisableTiming);
    cudaEventCreateWithFlags(&evVt,     cudaEventDisableTiming);

    // ---- stream 0: input conversion ----
    const int nIn16 = BT * DH / 8;            // query/value
    const int nW16  = DH * ND / 8;            // Wq/Wk
    half_perm2<<<dim3(nIn16 / 256, 2), 256>>>(query, qr, value, vr, nIn16);
    cudaEventRecord(evIn, 0);

    // ---- s2: wvt / yz / uw (independent of stream-0 GEMM chain) ----
    cudaStreamWaitEvent(s2, evIn, 0);
    transpose_wv<<<dim3(ND / 32, DH / 32), dim3(32, 8), 0, s2>>>(Wv, wvt);
    yz_kernel<<<1025, 256, 0, s2>>>(Wq, Wk, bq, bk, y, zv, c);
    uw_kernel<<<dim3(BT / 8, 2), 256, 0, s2>>>(qr, vr, y, zv, c, u, w);
    cudaEventRecord(evPre, s2);

    // ---- stream 0: weight conversion, M, q-hat ----
    half_perm2<<<dim3(nW16 / 256, 2), 256>>>(Wq, wq16, Wk, wk16, nW16);

    GemmArgs a;

    // M-GEMM: Mt[h*512+e][d] = sum_f Wk[e, h*512+f] * Wq[d, h*512+f]
    a = { wk16, 0, 512, ND,
          wq16, 0, 512, ND,
          mt, 0, 512LL * 512, 512,
          DH, 8, nullptr, nullptr, 0, 1.0f, 0, 1 };
    gemm_tc<<<dim3(4, 4, 8), 256, SMEM_BYTES>>>(a);

    // q-hat GEMM: g_q[i][h*512+e] = sum_d qr[i][d] * Mt[h*512+e][d]
    a = { qr, 0, 0, DH,
          mt, 0, 0, DH,
          q, 0, 0, ND,
          DH, 1, nullptr, nullptr, 0, 1.0f, 0, 1 };
    gemm_tc<<<dim3(ND / TN, BT / TM, 1), 256, SMEM_BYTES>>>(a);

    // scores needs u/w from s2
    cudaStreamWaitEvent(0, evPre, 0);

    // scores = scale*(qhat @ value^T + u + w + c)  (causal skip; fp16 perm out)
    a = { q, (long long)T_ * ND, 512, ND,
          vr, (long long)T_ * DH, 0, DH,
          p, 8LL * T_ * T_, (long long)T_ * T_, T_,
          DH, H_, u, w, 3, 0.044194173824159216f, 1, 1 };
    gemm_tc<<<dim3(T_ / TN, T_ / TM, B_ * H_), 256, SMEM_BYTES>>>(a);
    cudaEventRecord(evScores, 0);

    // ---- s2: vt GEMM runs concurrently with softmax (compute ∥ bandwidth) ----
    cudaStreamWaitEvent(s2, evScores, 0);
    a = { wvt, 0, 0, DH,
          vr, (long long)T_ * DH, 0, DH,
          vt, (long long)ND * T_, 0, T_,
          DH, 1, bv, nullptr, 2, 1.0f, 0, 1 };
    gemm_tc<<<dim3(T_ / TN, ND / TM, B_), 256, SMEM_BYTES, s2>>>(a);
    cudaEventRecord(evVt, s2);

    // ---- stream 0: softmax ----
    softmax_rows<<<dim3(T_, B_ * H_), 128>>>(p);

    // ---- join: PV needs probs (stream 0) + vt (s2) ----
    cudaStreamWaitEvent(0, evVt, 0);

    // out = P @ V   (K bounded at m0+128; fp32 plain out)
    a = { p, 8LL * T_ * T_, (long long)T_ * T_, T_,
          vt, (long long)ND * T_, (long long)DH * T_, T_,
          out, (long long)T_ * ND, DH, ND,
          T_, H_, nullptr, nullptr, 0, 1.0f, 2, 0 };
    gemm_tc<<<dim3(DH / TN, T_ / TM, B_ * H_), 256, SMEM_BYTES>>>(a);
}